// round 12
// baseline (speedup 1.0000x reference)
#include <cuda_runtime.h>
#include <cuda_fp16.h>

#define N_NODES 100000
#define DIM 64
#define N_EDGES 1250000
#define CAP 64          // bucket slots per node; Poisson(12.5) max degree ~40
#define H2PR 32         // __half2 per row (64 halves = 128B)

// Static scratch (zero-initialized at module load; pull re-zeroes g_cnt/g_novf
// after use so every graph replay starts from a clean state).
// +8 pad: pipelined prefetch may read up to two int4 past the last bucket.
__device__ int g_cnt[N_NODES];
__device__ int g_bucket[(size_t)N_NODES * CAP + 8];
__device__ int g_novf;
__device__ int g_ovf_src[N_EDGES];
__device__ int g_ovf_dst[N_EDGES];
__device__ __half2 g_xh[(size_t)N_NODES * H2PR];   // x rows in fp16 (128B each)

#define FILL_THREADS (N_EDGES / 4)                     // 312500
#define FILL_BLOCKS ((FILL_THREADS + 255) / 256)       // 1221
#define CONV_ITEMS (N_NODES * DIM / 4)                 // 1.6M float4s
#define CONV_BLOCKS ((CONV_ITEMS + 255) / 256)         // 6250

// Fused prep: fill blocks claim bucket slots (atomic-bound), convert blocks
// turn x into fp16 rows (BW-bound) — they overlap on the chip.
__global__ void prep_kernel(const float* __restrict__ x,
                            const int* __restrict__ edge_index) {
    if (blockIdx.x < FILL_BLOCKS) {
        int t = blockIdx.x * blockDim.x + threadIdx.x;
        if (t >= FILL_THREADS) return;
        int4 s4 = reinterpret_cast<const int4*>(edge_index)[t];
        int4 d4 = reinterpret_cast<const int4*>(edge_index + N_EDGES)[t];
        int ss[4] = {s4.x, s4.y, s4.z, s4.w};
        int dd[4] = {d4.x, d4.y, d4.z, d4.w};
        #pragma unroll
        for (int k = 0; k < 4; k++) {
            int src = ss[k], dst = dd[k];
            int slot = atomicAdd(&g_cnt[dst], 1);
            if (slot < CAP) {
                g_bucket[(size_t)dst * CAP + slot] = src;
            } else {
                int q = atomicAdd(&g_novf, 1);
                if (q < N_EDGES) { g_ovf_src[q] = src; g_ovf_dst[q] = dst; }
            }
        }
    } else {
        int i = (blockIdx.x - FILL_BLOCKS) * blockDim.x + threadIdx.x;
        if (i >= CONV_ITEMS) return;
        float4 f = reinterpret_cast<const float4*>(x)[i];
        __half2 h0 = __floats2half2_rn(f.x, f.y);
        __half2 h1 = __floats2half2_rn(f.z, f.w);
        uint2 u;
        u.x = *reinterpret_cast<unsigned*>(&h0);
        u.y = *reinterpret_cast<unsigned*>(&h1);
        reinterpret_cast<uint2*>(g_xh)[i] = u;
    }
}

// Warp per node. Uniform (broadcast) index quads, 8 fp16-row gathers in flight,
// fp32 accumulation. out = relu(2*agg/||agg||) — the mean's 1/cnt cancels.
__global__ void pull_kernel(float* __restrict__ out) {
    int gtid = blockIdx.x * blockDim.x + threadIdx.x;
    int node = gtid >> 5;
    int lane = gtid & 31;
    if (node >= N_NODES) return;

    const unsigned FULL = 0xFFFFFFFFu;
    int cnt = g_cnt[node];                         // uniform broadcast load
    int m = cnt < CAP ? cnt : CAP;

    const int* bp = g_bucket + (size_t)node * CAP; // 256B-aligned
    const __half2* xb = g_xh + lane;               // lane's half2 column

    float ax0 = 0.f, ay0 = 0.f, ax1 = 0.f, ay1 = 0.f;
    float ax2 = 0.f, ay2 = 0.f, ax3 = 0.f, ay3 = 0.f;

    int4 s = *reinterpret_cast<const int4*>(bp);   // prefetched quad (always valid)
    int j = 0;

    // 8-edge body: two quads, 8 independent 4B gathers in flight.
    for (; j + 8 <= m; j += 8) {
        int4 q0 = s;
        int4 q1 = *reinterpret_cast<const int4*>(bp + j + 4);
        s = *reinterpret_cast<const int4*>(bp + j + 8);      // prefetch (pad-safe)
        __half2 h0 = xb[(size_t)q0.x * H2PR];
        __half2 h1 = xb[(size_t)q0.y * H2PR];
        __half2 h2 = xb[(size_t)q0.z * H2PR];
        __half2 h3 = xb[(size_t)q0.w * H2PR];
        __half2 h4 = xb[(size_t)q1.x * H2PR];
        __half2 h5 = xb[(size_t)q1.y * H2PR];
        __half2 h6 = xb[(size_t)q1.z * H2PR];
        __half2 h7 = xb[(size_t)q1.w * H2PR];
        float2 v0 = __half22float2(h0); ax0 += v0.x; ay0 += v0.y;
        float2 v1 = __half22float2(h1); ax1 += v1.x; ay1 += v1.y;
        float2 v2 = __half22float2(h2); ax2 += v2.x; ay2 += v2.y;
        float2 v3 = __half22float2(h3); ax3 += v3.x; ay3 += v3.y;
        float2 v4 = __half22float2(h4); ax0 += v4.x; ay0 += v4.y;
        float2 v5 = __half22float2(h5); ax1 += v5.x; ay1 += v5.y;
        float2 v6 = __half22float2(h6); ax2 += v6.x; ay2 += v6.y;
        float2 v7 = __half22float2(h7); ax3 += v7.x; ay3 += v7.y;
    }
    // 4-edge body.
    for (; j + 4 <= m; j += 4) {
        int4 cur = s;
        s = *reinterpret_cast<const int4*>(bp + j + 4);      // prefetch (pad-safe)
        __half2 h0 = xb[(size_t)cur.x * H2PR];
        __half2 h1 = xb[(size_t)cur.y * H2PR];
        __half2 h2 = xb[(size_t)cur.z * H2PR];
        __half2 h3 = xb[(size_t)cur.w * H2PR];
        float2 v0 = __half22float2(h0); ax0 += v0.x; ay0 += v0.y;
        float2 v1 = __half22float2(h1); ax1 += v1.x; ay1 += v1.y;
        float2 v2 = __half22float2(h2); ax2 += v2.x; ay2 += v2.y;
        float2 v3 = __half22float2(h3); ax3 += v3.x; ay3 += v3.y;
    }
    // Tail (0..3): uses the already-prefetched quad, no further index loads.
    int r = m - j;
    if (r > 0) { float2 v = __half22float2(xb[(size_t)s.x * H2PR]); ax0 += v.x; ay0 += v.y; }
    if (r > 1) { float2 v = __half22float2(xb[(size_t)s.y * H2PR]); ax1 += v.x; ay1 += v.y; }
    if (r > 2) { float2 v = __half22float2(xb[(size_t)s.z * H2PR]); ax2 += v.x; ay2 += v.y; }

    float accx = (ax0 + ax1) + (ax2 + ax3);
    float accy = (ay0 + ay1) + (ay2 + ay3);

    // Overflow correctness path (normally dead: g_novf == 0).
    if (cnt > CAP) {
        int no = g_novf;
        if (no > N_EDGES) no = N_EDGES;
        for (int k = 0; k < no; k++) {
            if (g_ovf_dst[k] == node) {
                float2 v = __half22float2(xb[(size_t)g_ovf_src[k] * H2PR]);
                accx += v.x;
                accy += v.y;
            }
        }
    }

    // Reset state for the next graph replay (exclusive owner of this element).
    if (lane == 0) g_cnt[node] = 0;
    if (node == 0 && lane == 1) g_novf = 0;

    // ||agg|| reduce across the warp.
    float ss2 = accx * accx + accy * accy;
    #pragma unroll
    for (int off = 16; off > 0; off >>= 1)
        ss2 += __shfl_xor_sync(FULL, ss2, off);

    // out = relu(2 * agg / ||agg||). agg==0 -> 0 exactly, matching reference.
    float scale = 2.0f * rsqrtf(fmaxf(ss2, 1e-30f));
    float2 rr;
    rr.x = fmaxf(accx * scale, 0.0f);
    rr.y = fmaxf(accy * scale, 0.0f);
    reinterpret_cast<float2*>(out + (size_t)node * DIM)[lane] = rr;
}

extern "C" void kernel_launch(void* const* d_in, const int* in_sizes, int n_in,
                              void* d_out, int out_size) {
    const float* x = (const float*)d_in[0];
    const int* edge_index = (const int*)d_in[1];
    // d_in[2] = edge_weights: unused by the reference computation.
    float* out = (float*)d_out;

    {
        int blocks = FILL_BLOCKS + CONV_BLOCKS;  // fill blocks first (atomics start early)
        prep_kernel<<<blocks, 256>>>(x, edge_index);
    }
    {
        long long total = (long long)N_NODES * 32;
        int threads = 256;
        int blocks = (int)((total + threads - 1) / threads);
        pull_kernel<<<blocks, threads>>>(out);
    }
}